// round 1
// baseline (speedup 1.0000x reference)
#include <cuda_runtime.h>

// NeRF positional encoding:
//   x:   [rows, 4]   float32   (rows = 64*1024)
//   out: [rows, 768] float32
// out[row, k*64 + L*8 + 2c + s] = (s==0 ? sin : cos)(2^L * pi * x[row,c])
//   for k in [0,12), L in [0,8), c in [0,4), s in {0,1}
//
// One warp per row. Lane t:
//   q = t & 15  -> which float4 inside the 64-value block: q = 2L + (c_pair)
//   h = t >> 4  -> even/odd repetition index
// Each lane computes its float4 {sin(f*xa), cos(f*xa), sin(f*xb), cos(f*xb)}
// once (2 sincos) and stores it 6 times (reps h, h+2, ..., h+10).
// Per warp iteration: 32 lanes x 16B = 2048 contiguous bytes -> fully coalesced.

__global__ void __launch_bounds__(256)
nerf_pe_kernel(const float4* __restrict__ x, float4* __restrict__ out, int rows) {
    const int tid   = blockIdx.x * blockDim.x + threadIdx.x;
    const int gwarp = tid >> 5;          // row index
    const int lane  = tid & 31;
    if (gwarp >= rows) return;

    // Broadcast load of this row's 4 coords (16B, L1-cached, all lanes same addr)
    const float4 xv = __ldg(&x[gwarp]);

    const int q = lane & 15;             // 0..15: (L = q>>1, coord pair = q&1)
    const int h = lane >> 4;             // 0 or 1: repetition parity
    const int L = q >> 1;

    // 2^L * pi in f32: exact power-of-two scaling of f32 pi, matches reference
    const float f = 3.14159265358979323846f * (float)(1 << L);

    const float a = (q & 1) ? xv.z : xv.x;
    const float b = (q & 1) ? xv.w : xv.y;

    float s0, c0, s1, c1;
    sincosf(f * a, &s0, &c0);
    sincosf(f * b, &s1, &c1);
    const float4 v = make_float4(s0, c0, s1, c1);

    // out row = 768 floats = 192 float4. Rep r occupies float4 [r*16, r*16+16).
    float4* o = out + (size_t)gwarp * 192 + h * 16 + q;
    #pragma unroll
    for (int r = 0; r < 6; ++r) {
        o[r * 32] = v;                   // reps h, h+2, h+4, h+6, h+8, h+10
    }
}

extern "C" void kernel_launch(void* const* d_in, const int* in_sizes, int n_in,
                              void* d_out, int out_size) {
    const float4* x = (const float4*)d_in[0];
    float4* out = (float4*)d_out;
    const int rows = in_sizes[0] / 4;            // [rows, 4] coords

    const int threads = 256;                     // 8 warps = 8 rows per block
    const int total_threads = rows * 32;         // one warp per row
    const int blocks = (total_threads + threads - 1) / threads;

    nerf_pe_kernel<<<blocks, threads>>>(x, out, rows);
}